// round 15
// baseline (speedup 1.0000x reference)
#include <cuda_runtime.h>
#include <cuda_bf16.h>
#include <cuda_fp16.h>
#include <cstdint>

// Problem constants (fixed by the dataset)
#define NN      50000
#define EE      800000
#define IN_DIM  256
#define HEADS   8
#define C1      64
#define HC1     512          // HEADS*C1
#define C2      32
#define OUT_DIM 40
#define NEG_SLOPE 0.2f

#define SCAN_BLOCKS 49       // 49 * 1024 >= NN

// ---------------- scratch (device globals; no cudaMalloc allowed) ------------
__device__ __half g_xl1h[(size_t)NN * HC1];   // x @ W1  (fp16)
__device__ __half g_h1h [(size_t)NN * HC1];   // layer-1 output, relu (fp16)
__device__ __half g_xh  [(size_t)NN * IN_DIM];   // x in fp16
__device__ __half g_w1h [(size_t)IN_DIM * HC1];  // W1 fp16
__device__ __half g_w2hi[HC1 * C2];
__device__ __half g_w2lo[HC1 * C2];
__device__ __half g_xl2h[(size_t)NN * C2];    // layer-2 pre-act (fp16)
__device__ float g_as1[NN * HEADS];
__device__ float g_ad1[NN * HEADS];
__device__ float g_as2[NN], g_ad2[NN];
__device__ int   g_deg[NN];
__device__ int   g_incl[SCAN_BLOCKS * 1024];
__device__ int   g_bsum[SCAN_BLOCKS];
__device__ int   g_boff[SCAN_BLOCKS];
__device__ int   g_rowptr[NN + 1];
__device__ int   g_cursor[NN];
__device__ int   g_csrc[EE];

__device__ __forceinline__ float lrelu(float x) { return x > 0.f ? x : NEG_SLOPE * x; }

// ========================= PTX helpers =========================
__device__ __forceinline__ uint32_t smem_u32(const void* p) {
    uint32_t a;
    asm("{ .reg .u64 t; cvta.to.shared.u64 t, %1; cvt.u32.u64 %0, t; }" : "=r"(a) : "l"(p));
    return a;
}
__device__ __forceinline__ void ldsm_x4(uint32_t addr, uint32_t& r0, uint32_t& r1,
                                        uint32_t& r2, uint32_t& r3) {
    asm volatile("ldmatrix.sync.aligned.m8n8.x4.shared.b16 {%0,%1,%2,%3}, [%4];"
                 : "=r"(r0), "=r"(r1), "=r"(r2), "=r"(r3) : "r"(addr));
}
__device__ __forceinline__ void ldsm_x4_trans(uint32_t addr, uint32_t& r0, uint32_t& r1,
                                              uint32_t& r2, uint32_t& r3) {
    asm volatile("ldmatrix.sync.aligned.m8n8.x4.trans.shared.b16 {%0,%1,%2,%3}, [%4];"
                 : "=r"(r0), "=r"(r1), "=r"(r2), "=r"(r3) : "r"(addr));
}
__device__ __forceinline__ void mma_f16(float* d, const uint32_t* a, const uint32_t* b) {
    asm volatile(
        "mma.sync.aligned.m16n8k16.row.col.f32.f16.f16.f32 "
        "{%0,%1,%2,%3},{%4,%5,%6,%7},{%8,%9},{%0,%1,%2,%3};"
        : "+f"(d[0]), "+f"(d[1]), "+f"(d[2]), "+f"(d[3])
        : "r"(a[0]), "r"(a[1]), "r"(a[2]), "r"(a[3]), "r"(b[0]), "r"(b[1]));
}
__device__ __forceinline__ void cp16(uint32_t dst, const void* src, uint32_t sz) {
    asm volatile("cp.async.cg.shared.global [%0], [%1], 16, %2;"
                 :: "r"(dst), "l"(src), "r"(sz) : "memory");
}
// unpack 8 fp16 (one uint4) to 8 floats
__device__ __forceinline__ void unpack8(uint4 v, float* f) {
    float2 t;
    t = __half22float2(*(__half2*)&v.x); f[0] = t.x; f[1] = t.y;
    t = __half22float2(*(__half2*)&v.y); f[2] = t.x; f[3] = t.y;
    t = __half22float2(*(__half2*)&v.z); f[4] = t.x; f[5] = t.y;
    t = __half22float2(*(__half2*)&v.w); f[6] = t.x; f[7] = t.y;
}

// ===================== merged input prep kernel ================================
#define NXC (NN * IN_DIM / 4)
#define NWC (IN_DIM * HC1 / 4)
#define NW2C (HC1 * C2 / 4)
__global__ void split_all_kernel(const float* __restrict__ x, const float* __restrict__ w1,
                                 const float* __restrict__ w2) {
    int i = blockIdx.x * blockDim.x + threadIdx.x;
    if (i < NXC) {
        float4 v = ((const float4*)x)[i];
        __half2 a = __floats2half2_rn(v.x, v.y);
        __half2 b = __floats2half2_rn(v.z, v.w);
        ((uint2*)g_xh)[i] = make_uint2(*(uint32_t*)&a, *(uint32_t*)&b);
    } else if (i < NXC + NWC) {
        int k = i - NXC;
        float4 v = ((const float4*)w1)[k];
        __half2 a = __floats2half2_rn(v.x, v.y);
        __half2 b = __floats2half2_rn(v.z, v.w);
        ((uint2*)g_w1h)[k] = make_uint2(*(uint32_t*)&a, *(uint32_t*)&b);
    } else if (i < NXC + NWC + NW2C) {
        int k = i - NXC - NWC;
        float4 v = ((const float4*)w2)[k];
        __half h0 = __float2half_rn(v.x), h1 = __float2half_rn(v.y);
        __half h2 = __float2half_rn(v.z), h3 = __float2half_rn(v.w);
        __half l0 = __float2half_rn(v.x - __half2float(h0));
        __half l1 = __float2half_rn(v.y - __half2float(h1));
        __half l2 = __float2half_rn(v.z - __half2float(h2));
        __half l3 = __float2half_rn(v.w - __half2float(h3));
        __half2 p0 = __halves2half2(h0, h1), p1 = __halves2half2(h2, h3);
        __half2 q0 = __halves2half2(l0, l1), q1 = __halves2half2(l2, l3);
        ((uint2*)g_w2hi)[k] = make_uint2(*(uint32_t*)&p0, *(uint32_t*)&p1);
        ((uint2*)g_w2lo)[k] = make_uint2(*(uint32_t*)&q0, *(uint32_t*)&q1);
    }
}

// ======== GEMM1: xl1 = x @ W1, pure fp16, cp.async 3-stage pipeline ==========
// ny selects the N half (128 cols = 2 heads... actually 128 cols = heads ny*2..ny*2+1? No:
// ny in {0,1}: cols [ny*128*?]. HC1=512, two launches of 256 cols each: ny*256.
// Wait: original grid.y = HC1/128 = 4? No, original was (NN/128, HC1/128=4)?? It was
// HC1/128 = 4 tiles... but code used blockIdx.y in {0,1} with warpN 64*2=128 cols...
// Original: grid.y = HC1/128 = 4? HC1=512 -> 512/128 = 4. But epilogue used
// h = blockIdx.y*2 + (wid>>2), covering 8 heads over 4 y-values. Here ny in {0..3}
// would need 4 launches. Instead: one launch covers TWO y-tiles via blockIdx.y in {0,1}
// plus base: y = nyBase*2 + blockIdx.y. Launch 1: nyBase=0 (heads 0-3), launch 2: nyBase=1.
#define ASTR 40     // fp16 per A smem row (32 + 8 pad)
#define BSTR 136    // fp16 per B smem row (128 + 8 pad)
#define OFF_A   0
#define OFF_B   10240
#define STAGE   18944
#define GEMM1_SMEM (3 * STAGE)

__global__ void __launch_bounds__(256, 2) gemm1_mma_kernel(const float* __restrict__ attS1,
                                                           const float* __restrict__ attD1,
                                                           int nyBase) {
    extern __shared__ __align__(16) char smem[];
    const uint32_t sbase = smem_u32(smem);
    const int tid = threadIdx.x, wid = tid >> 5, lane = tid & 31;
    const int warpM = (wid & 3) * 32;
    const int warpN = (wid >> 2) * 64;
    const int mBase = blockIdx.x * 128;
    const int ny = nyBase * 2 + blockIdx.y;
    const int nBase = ny * 128;

    float acc[2][8][4];
#pragma unroll
    for (int mi = 0; mi < 2; mi++)
#pragma unroll
        for (int ni = 0; ni < 8; ni++)
#pragma unroll
            for (int q = 0; q < 4; q++) acc[mi][ni][q] = 0.f;

    auto load_stage = [&](int ch, int buf) {
        const int k0 = ch * 32;
        const uint32_t sb = sbase + buf * STAGE;
#pragma unroll
        for (int it = 0; it < 2; it++) {
            int chunk = it * 256 + tid;          // 512 chunks (A)
            int r = chunk >> 2, c = (chunk & 3) * 8;
            int gr = mBase + r;
            uint32_t sz = (gr < NN) ? 16u : 0u;
            int grc = gr < NN ? gr : NN - 1;
            uint32_t so = (uint32_t)(r * ASTR + c) * 2;
            cp16(sb + OFF_A + so, &g_xh[(size_t)grc * IN_DIM + k0 + c], sz);
        }
#pragma unroll
        for (int it = 0; it < 2; it++) {
            int chunk = it * 256 + tid;          // 512 chunks (B)
            int r = chunk >> 4, c = (chunk & 15) * 8;
            uint32_t so = (uint32_t)(r * BSTR + c) * 2;
            cp16(sb + OFF_B + so, &g_w1h[(size_t)(k0 + r) * HC1 + nBase + c], 16);
        }
        asm volatile("cp.async.commit_group;" ::: "memory");
    };

    load_stage(0, 0);
    load_stage(1, 1);
    for (int ch = 0; ch < 8; ch++) {
        if (ch < 7) {
            asm volatile("cp.async.wait_group 1;" ::: "memory");
        } else {
            asm volatile("cp.async.wait_group 0;" ::: "memory");
        }
        __syncthreads();
        if (ch + 2 < 8) load_stage(ch + 2, (ch + 2) % 3);
        const uint32_t sb = sbase + (ch % 3) * STAGE;
#pragma unroll
        for (int ks = 0; ks < 2; ks++) {
            uint32_t av[2][4];
#pragma unroll
            for (int mi = 0; mi < 2; mi++) {
                int row = warpM + mi * 16 + (lane & 15);
                int col = ks * 16 + (lane >> 4) * 8;
                uint32_t off = (uint32_t)(row * ASTR + col) * 2;
                ldsm_x4(sb + OFF_A + off, av[mi][0], av[mi][1], av[mi][2], av[mi][3]);
            }
            uint32_t bv[8][2];
#pragma unroll
            for (int np = 0; np < 4; np++) {
                int krow = ks * 16 + (lane & 15);
                int col = warpN + np * 16 + (lane >> 4) * 8;
                uint32_t off = (uint32_t)(krow * BSTR + col) * 2;
                ldsm_x4_trans(sb + OFF_B + off, bv[np * 2][0], bv[np * 2][1],
                              bv[np * 2 + 1][0], bv[np * 2 + 1][1]);
            }
#pragma unroll
            for (int mi = 0; mi < 2; mi++)
#pragma unroll
                for (int ni = 0; ni < 8; ni++)
                    mma_f16(acc[mi][ni], av[mi], bv[ni]);
        }
    }

    // ---- epilogue 1: store xl1 (fp16) ----
#pragma unroll
    for (int mi = 0; mi < 2; mi++) {
#pragma unroll
        for (int ni = 0; ni < 8; ni++) {
            int row0 = mBase + warpM + mi * 16 + (lane >> 2);
            int col = nBase + warpN + ni * 8 + (lane & 3) * 2;
            if (row0 < NN)
                *(__half2*)(&g_xl1h[(size_t)row0 * HC1 + col]) =
                    __floats2half2_rn(acc[mi][ni][0], acc[mi][ni][1]);
            int row1 = row0 + 8;
            if (row1 < NN)
                *(__half2*)(&g_xl1h[(size_t)row1 * HC1 + col]) =
                    __floats2half2_rn(acc[mi][ni][2], acc[mi][ni][3]);
        }
    }

    // ---- epilogue 2: fused a_src / a_dst (warp owns one complete head) ----
    {
        const int h = ny * 2 + (wid >> 2);
        float sS[8][2], sD[8][2];
        int cb = h * C1 + (lane & 3) * 2;
#pragma unroll
        for (int ni = 0; ni < 8; ni++) {
            sS[ni][0] = __ldg(&attS1[cb + ni * 8]);
            sS[ni][1] = __ldg(&attS1[cb + ni * 8 + 1]);
            sD[ni][0] = __ldg(&attD1[cb + ni * 8]);
            sD[ni][1] = __ldg(&attD1[cb + ni * 8 + 1]);
        }
#pragma unroll
        for (int mi = 0; mi < 2; mi++) {
            float rs0 = 0.f, rs1 = 0.f, rd0 = 0.f, rd1 = 0.f;
#pragma unroll
            for (int ni = 0; ni < 8; ni++) {
                rs0 = fmaf(acc[mi][ni][0], sS[ni][0], fmaf(acc[mi][ni][1], sS[ni][1], rs0));
                rd0 = fmaf(acc[mi][ni][0], sD[ni][0], fmaf(acc[mi][ni][1], sD[ni][1], rd0));
                rs1 = fmaf(acc[mi][ni][2], sS[ni][0], fmaf(acc[mi][ni][3], sS[ni][1], rs1));
                rd1 = fmaf(acc[mi][ni][2], sD[ni][0], fmaf(acc[mi][ni][3], sD[ni][1], rd1));
            }
#pragma unroll
            for (int off = 1; off <= 2; off <<= 1) {
                rs0 += __shfl_xor_sync(0xffffffffu, rs0, off);
                rd0 += __shfl_xor_sync(0xffffffffu, rd0, off);
                rs1 += __shfl_xor_sync(0xffffffffu, rs1, off);
                rd1 += __shfl_xor_sync(0xffffffffu, rd1, off);
            }
            if ((lane & 3) == 0) {
                int row0 = mBase + warpM + mi * 16 + (lane >> 2);
                if (row0 < NN) { g_as1[row0 * 8 + h] = rs0; g_ad1[row0 * 8 + h] = rd0; }
                int row1 = row0 + 8;
                if (row1 < NN) { g_as1[row1 * 8 + h] = rs1; g_ad1[row1 * 8 + h] = rd1; }
            }
        }
    }
}

// ---------------------------- CSR construction -------------------------------
__global__ void hist_kernel(const int* __restrict__ dst) {
    int e = blockIdx.x * blockDim.x + threadIdx.x;
    if (e < EE) atomicAdd(&g_deg[dst[e]], 1);
}
__global__ void scanA_kernel() {
    __shared__ int sh[1024];
    int i = blockIdx.x * 1024 + threadIdx.x;
    int v = (i < NN) ? g_deg[i] : 0;
    sh[threadIdx.x] = v;
    __syncthreads();
#pragma unroll
    for (int off = 1; off < 1024; off <<= 1) {
        int t = (threadIdx.x >= off) ? sh[threadIdx.x - off] : 0;
        __syncthreads();
        sh[threadIdx.x] += t;
        __syncthreads();
    }
    g_incl[i] = sh[threadIdx.x];
    if (threadIdx.x == 1023) g_bsum[blockIdx.x] = sh[1023];
}
__global__ void scanB_kernel() {   // 1 block, 64 threads
    __shared__ int sh[64];
    int t = threadIdx.x;
    int v = (t < SCAN_BLOCKS) ? g_bsum[t] : 0;
    sh[t] = v;
    __syncthreads();
#pragma unroll
    for (int off = 1; off < 64; off <<= 1) {
        int u = (t >= off) ? sh[t - off] : 0;
        __syncthreads();
        sh[t] += u;
        __syncthreads();
    }
    if (t < SCAN_BLOCKS) g_boff[t] = sh[t] - v;   // exclusive
}
__global__ void scanC_kernel() {
    int i = blockIdx.x * 1024 + threadIdx.x;
    if (i < NN) {
        int ex = g_boff[blockIdx.x] + g_incl[i] - g_deg[i];
        g_rowptr[i] = ex;
        g_cursor[i] = ex;
    }
    if (i == 0) g_rowptr[NN] = EE;
}
__global__ void scatter_kernel(const int* __restrict__ src, const int* __restrict__ dst) {
    int e = blockIdx.x * blockDim.x + threadIdx.x;
    if (e >= EE) return;
    int d = dst[e];
    int pos = atomicAdd(&g_cursor[d], 1);
    g_csrc[pos] = src[e];
}

// ---- layer-1 fused softmax+aggregation, per head-half ------------------------
// warp per node; lane covers (head_local = lane>>3) in [0,4), 8 cols at e8*8.
__global__ void agg1_kernel(const float* __restrict__ b1, int hh) {
    int w = (blockIdx.x * blockDim.x + threadIdx.x) >> 5;
    int lane = threadIdx.x & 31;
    if (w >= NN) return;
    const int hl = lane >> 3;                // 0..3
    const int head = hh * 4 + hl;
    const int e8 = lane & 7;
    const int idx8 = w * 8 + head;
    const float ad = g_ad1[idx8];
    const float pself = __expf(lrelu(g_as1[idx8] + ad));
    const uint32_t off = hh * 256 + hl * 64 + e8 * 8;  // fp16 offset within row

    float acc[8];
    {
        uint4 v = *(const uint4*)(g_xl1h + (size_t)w * HC1 + off);
        unpack8(v, acc);
#pragma unroll
        for (int i = 0; i < 8; i++) acc[i] *= pself;
    }
    float dacc = 0.f;

    const int beg = g_rowptr[w], end = g_rowptr[w + 1];
    const int gb = lane & 24;    // lane group base (8-lane groups)

    int s_cur = 0; float a_cur = 0.f;
    {
        int j = beg + e8;
        if (j < end) { s_cur = g_csrc[j]; a_cur = __ldg(&g_as1[s_cur * 8 + head]); }
    }
    for (int j0 = beg; j0 < end; j0 += 8) {
        int s_nxt = 0; float a_nxt = 0.f;
        int jn = j0 + 8 + e8;
        if (jn < end) { s_nxt = g_csrc[jn]; a_nxt = __ldg(&g_as1[s_nxt * 8 + head]); }

        bool valid = (j0 + e8) < end;
        float p_l = valid ? __expf(lrelu(a_cur + ad)) : 0.f;
        dacc += p_l;
        int cnt = end - j0;
#pragma unroll
        for (int t = 0; t < 8; t++) {
            if (t < cnt) {
                float p = __shfl_sync(0xffffffffu, p_l, gb | t);
                int   s = __shfl_sync(0xffffffffu, s_cur, gb | t);
                uint4 u = *(const uint4*)(g_xl1h + (size_t)s * HC1 + off);
                float bq[8];
                unpack8(u, bq);
#pragma unroll
                for (int i = 0; i < 8; i++) acc[i] = fmaf(p, bq[i], acc[i]);
            }
        }
        s_cur = s_nxt; a_cur = a_nxt;
    }
    dacc += __shfl_xor_sync(0xffffffffu, dacc, 1);
    dacc += __shfl_xor_sync(0xffffffffu, dacc, 2);
    dacc += __shfl_xor_sync(0xffffffffu, dacc, 4);
    float inv = 1.f / (dacc + pself + 1e-16f);

    float bv[8];
    {
        float4 t0 = *(const float4*)(b1 + off);
        float4 t1 = *(const float4*)(b1 + off + 4);
        bv[0] = t0.x; bv[1] = t0.y; bv[2] = t0.z; bv[3] = t0.w;
        bv[4] = t1.x; bv[5] = t1.y; bv[6] = t1.z; bv[7] = t1.w;
    }
    uint32_t r[4];
#pragma unroll
    for (int i = 0; i < 4; i++) {
        float f0 = fmaxf(fmaf(acc[2 * i],     inv, bv[2 * i]),     0.f);
        float f1 = fmaxf(fmaf(acc[2 * i + 1], inv, bv[2 * i + 1]), 0.f);
        __half2 hh2 = __floats2half2_rn(f0, f1);
        r[i] = *(uint32_t*)&hh2;
    }
    *(uint4*)(g_h1h + (size_t)w * HC1 + off) = make_uint4(r[0], r[1], r[2], r[3]);
}

// ==== GEMM2: xl2 = h1 @ W2 (rows [nodeBeg,nodeEnd)), fp16 A + fp16 hi/lo B ===
#define A2STR 40
#define B2STR 40
__global__ void __launch_bounds__(256) gemm2_mma_kernel(const float* __restrict__ attS2,
                                                        const float* __restrict__ attD2,
                                                        int nodeBeg, int nodeEnd) {
    __shared__ __align__(16) __half sA[128 * A2STR];
    __shared__ __align__(16) __half sBhi[32 * B2STR], sBlo[32 * B2STR];
    const int tid = threadIdx.x, wid = tid >> 5, lane = tid & 31;
    const int mBase = nodeBeg + blockIdx.x * 128;
    const int warpM = wid * 16;

    const int ar = tid >> 1, ak = (tid & 1) * 16;
    int grow = mBase + ar; if (grow >= nodeEnd) grow = nodeEnd - 1;
    const __half* abase = g_h1h + (size_t)grow * HC1 + ak;
    const bool bhi_role = tid < 128;
    const int bk = (tid & 127) >> 2, bseg = (tid & 3) * 8;
    const __half* bsrc = (bhi_role ? g_w2hi : g_w2lo) + bk * C2 + bseg;

    float acc[4][4];
#pragma unroll
    for (int ni = 0; ni < 4; ni++)
#pragma unroll
        for (int q = 0; q < 4; q++) acc[ni][q] = 0.f;

    uint4 ra0 = *(const uint4*)(abase);
    uint4 ra1 = *(const uint4*)(abase + 8);
    uint4 rb = *(const uint4*)bsrc;

    const uint32_t sAB = smem_u32(sA);
    const uint32_t sBhiB = smem_u32(sBhi), sBloB = smem_u32(sBlo);

    for (int ch = 0; ch < 16; ch++) {
        *(uint4*)(&sA[ar * A2STR + ak])     = ra0;
        *(uint4*)(&sA[ar * A2STR + ak + 8]) = ra1;
        __half* bdst = (bhi_role ? sBhi : sBlo) + bk * B2STR + bseg;
        *(uint4*)bdst = rb;
        __syncthreads();
        if (ch < 15) {
            const __half* an = abase + (ch + 1) * 32;
            ra0 = *(const uint4*)(an);
            ra1 = *(const uint4*)(an + 8);
            rb = *(const uint4*)(bsrc + (size_t)(ch + 1) * 32 * C2);
        }
#pragma unroll
        for (int ks = 0; ks < 2; ks++) {
            uint32_t av[4];
            int row = warpM + (lane & 15);
            int col = ks * 16 + (lane >> 4) * 8;
            uint32_t offA = (uint32_t)(row * A2STR + col) * 2;
            ldsm_x4(sAB + offA, av[0], av[1], av[2], av[3]);
            uint32_t bh[4][2], bl[4][2];
            int krow = ks * 16 + (lane & 15);
#pragma unroll
            for (int np = 0; np < 2; np++) {
                int bcol = np * 16 + (lane >> 4) * 8;
                uint32_t offB = (uint32_t)(krow * B2STR + bcol) * 2;
                ldsm_x4_trans(sBhiB + offB, bh[np * 2][0], bh[np * 2][1],
                              bh[np * 2 + 1][0], bh[np * 2 + 1][1]);
                ldsm_x4_trans(sBloB + offB, bl[np * 2][0], bl[np * 2][1],
                              bl[np * 2 + 1][0], bl[np * 2 + 1][1]);
            }
#pragma unroll
            for (int ni = 0; ni < 4; ni++) {
                mma_f16(acc[ni], av, bh[ni]);
                mma_f16(acc[ni], av, bl[ni]);
            }
        }
        __syncthreads();
    }

    int row0 = mBase + warpM + (lane >> 2);
    int row1 = row0 + 8;
    float rs0 = 0.f, rd0 = 0.f, rs1 = 0.f, rd1 = 0.f;
#pragma unroll
    for (int ni = 0; ni < 4; ni++) {
        int col = ni * 8 + (lane & 3) * 2;
        if (row0 < nodeEnd)
            *(__half2*)(&g_xl2h[(size_t)row0 * C2 + col]) =
                __floats2half2_rn(acc[ni][0], acc[ni][1]);
        if (row1 < nodeEnd)
            *(__half2*)(&g_xl2h[(size_t)row1 * C2 + col]) =
                __floats2half2_rn(acc[ni][2], acc[ni][3]);
        float s0 = __ldg(&attS2[col]), s1 = __ldg(&attS2[col + 1]);
        float d0 = __ldg(&attD2[col]), d1 = __ldg(&attD2[col + 1]);
        rs0 = fmaf(acc[ni][0], s0, fmaf(acc[ni][1], s1, rs0));
        rd0 = fmaf(acc[ni][0], d0, fmaf(acc[ni][1], d1, rd0));
        rs1 = fmaf(acc[ni][2], s0, fmaf(acc[ni][3], s1, rs1));
        rd1 = fmaf(acc[ni][2], d0, fmaf(acc[ni][3], d1, rd1));
    }
#pragma unroll
    for (int off = 1; off <= 2; off <<= 1) {
        rs0 += __shfl_xor_sync(0xffffffffu, rs0, off);
        rd0 += __shfl_xor_sync(0xffffffffu, rd0, off);
        rs1 += __shfl_xor_sync(0xffffffffu, rs1, off);
        rd1 += __shfl_xor_sync(0xffffffffu, rd1, off);
    }
    if ((lane & 3) == 0) {
        if (row0 < nodeEnd) { g_as2[row0] = rs0; g_ad2[row0] = rd0; }
        if (row1 < nodeEnd) { g_as2[row1] = rs1; g_ad2[row1] = rd1; }
    }
}

// ---- layer-2 fused softmax+aggregation + fc head: warp per node --------------
__global__ void __launch_bounds__(256) agg2_kernel(const float* __restrict__ b2,
                                                   const float* __restrict__ fcW,
                                                   const float* __restrict__ fcb,
                                                   float* __restrict__ out) {
    __shared__ float fs[C2 * OUT_DIM];
    __shared__ float fb[OUT_DIM];
    for (int i = threadIdx.x; i < C2 * OUT_DIM; i += 256) fs[i] = fcW[i];
    if (threadIdx.x < OUT_DIM) fb[threadIdx.x] = fcb[threadIdx.x];
    __syncthreads();

    int w = (blockIdx.x * blockDim.x + threadIdx.x) >> 5;
    int lane = threadIdx.x & 31;
    if (w >= NN) return;
    float ad = g_ad2[w];
    float pself = __expf(lrelu(g_as2[w] + ad));
    float acc0 = pself * __half2float(g_xl2h[(size_t)w * C2 + lane]);
    float acc1 = 0.f;
    float dacc = 0.f;
    const int beg = g_rowptr[w], end = g_rowptr[w + 1];

    int s_cur = 0; float a_cur = 0.f;
    {
        int j = beg + lane;
        if (j < end) { s_cur = g_csrc[j]; a_cur = __ldg(&g_as2[s_cur]); }
    }
    int j0 = beg;
    for (; j0 + 32 <= end; j0 += 32) {
        int s_nxt = 0; float a_nxt = 0.f;
        int jn = j0 + 32 + lane;
        if (jn < end) { s_nxt = g_csrc[jn]; a_nxt = __ldg(&g_as2[s_nxt]); }
        float p_l = __expf(lrelu(a_cur + ad));
        dacc += p_l;
#pragma unroll
        for (int t = 0; t < 32; t += 2) {
            float p0 = __shfl_sync(0xffffffffu, p_l, t);
            int   q0 = __shfl_sync(0xffffffffu, s_cur, t);
            float p1 = __shfl_sync(0xffffffffu, p_l, t + 1);
            int   q1 = __shfl_sync(0xffffffffu, s_cur, t + 1);
            acc0 = fmaf(p0, __half2float(g_xl2h[(size_t)q0 * C2 + lane]), acc0);
            acc1 = fmaf(p1, __half2float(g_xl2h[(size_t)q1 * C2 + lane]), acc1);
        }
        s_cur = s_nxt; a_cur = a_nxt;
    }
    if (j0 < end) {
        bool valid = (j0 + lane) < end;
        float p_l = valid ? __expf(lrelu(a_cur + ad)) : 0.f;
        dacc += p_l;
        int cnt = end - j0;
        for (int t = 0; t < cnt; t++) {
            float p = __shfl_sync(0xffffffffu, p_l, t);
            int   s = __shfl_sync(0xffffffffu, s_cur, t);
            acc0 = fmaf(p, __half2float(g_xl2h[(size_t)s * C2 + lane]), acc0);
        }
    }
    float acc = acc0 + acc1;
#pragma unroll
    for (int off = 16; off; off >>= 1) dacc += __shfl_xor_sync(0xffffffffu, dacc, off);
    float inv = 1.f / (dacc + pself + 1e-16f);
    float emb = fmaxf(fmaf(acc, inv, b2[lane]), 0.f);
    out[(size_t)w * C2 + lane] = emb;

    float l1 = fb[lane];
    float l2 = (lane < OUT_DIM - 32) ? fb[32 + lane] : 0.f;
#pragma unroll
    for (int c = 0; c < C2; c++) {
        float e = __shfl_sync(0xffffffffu, emb, c);
        l1 = fmaf(e, fs[c * OUT_DIM + lane], l1);
        if (lane < OUT_DIM - 32) l2 = fmaf(e, fs[c * OUT_DIM + 32 + lane], l2);
    }
    float* lg = out + (size_t)NN * C2 + (size_t)w * OUT_DIM;
    lg[lane] = l1;
    if (lane < OUT_DIM - 32) lg[32 + lane] = l2;
}

// ------------------------------------------------------------------------------
extern "C" void kernel_launch(void* const* d_in, const int* in_sizes, int n_in,
                              void* d_out, int out_size) {
    const float* x     = (const float*)d_in[0];
    const int*   ei    = (const int*)  d_in[1];
    const float* W1    = (const float*)d_in[2];
    const float* attS1 = (const float*)d_in[3];
    const float* attD1 = (const float*)d_in[4];
    const float* b1    = (const float*)d_in[5];
    const float* W2    = (const float*)d_in[6];
    const float* attS2 = (const float*)d_in[7];
    const float* attD2 = (const float*)d_in[8];
    const float* b2    = (const float*)d_in[9];
    const float* fcW   = (const float*)d_in[10];
    const float* fcb   = (const float*)d_in[11];
    float* out = (float*)d_out;

    const int* src = ei;
    const int* dst = ei + EE;

    static cudaStream_t sB = [] { cudaStream_t s; cudaStreamCreateWithFlags(&s, cudaStreamNonBlocking); return s; }();
    static cudaEvent_t evFork = [] { cudaEvent_t e; cudaEventCreateWithFlags(&e, cudaEventDisableTiming); return e; }();
    static cudaEvent_t evCSR  = [] { cudaEvent_t e; cudaEventCreateWithFlags(&e, cudaEventDisableTiming); return e; }();
    static cudaEvent_t evA    = [] { cudaEvent_t e; cudaEventCreateWithFlags(&e, cudaEventDisableTiming); return e; }();
    static cudaEvent_t evH0   = [] { cudaEvent_t e; cudaEventCreateWithFlags(&e, cudaEventDisableTiming); return e; }();
    static cudaEvent_t evX2   = [] { cudaEvent_t e; cudaEventCreateWithFlags(&e, cudaEventDisableTiming); return e; }();

    cudaFuncSetAttribute(gemm1_mma_kernel, cudaFuncAttributeMaxDynamicSharedMemorySize,
                         GEMM1_SMEM);

    // ---- fork: CSR chain on stream B ----
    cudaEventRecord(evFork, 0);
    cudaStreamWaitEvent(sB, evFork, 0);

    void* degp = nullptr;
    cudaGetSymbolAddress(&degp, g_deg);
    cudaMemsetAsync(degp, 0, NN * sizeof(int), sB);
    hist_kernel<<<(EE + 255) / 256, 256, 0, sB>>>(dst);
    scanA_kernel<<<SCAN_BLOCKS, 1024, 0, sB>>>();
    scanB_kernel<<<1, 64, 0, sB>>>();
    scanC_kernel<<<SCAN_BLOCKS, 1024, 0, sB>>>();
    scatter_kernel<<<(EE + 255) / 256, 256, 0, sB>>>(src, dst);
    cudaEventRecord(evCSR, sB);

    // ---- main stream: merged split + gemm1 first head-half ----
    split_all_kernel<<<(NXC + NWC + NW2C + 255) / 256, 256>>>(x, W1, W2);
    {
        dim3 grid((NN + 127) / 128, 2);
        gemm1_mma_kernel<<<grid, 256, GEMM1_SMEM>>>(attS1, attD1, 0);   // heads 0-3
        cudaEventRecord(evA, 0);
        gemm1_mma_kernel<<<grid, 256, GEMM1_SMEM>>>(attS1, attD1, 1);   // heads 4-7
    }

    // ---- agg1 hh=0 on stream B (overlaps gemm1 heads 4-7) ----
    cudaStreamWaitEvent(sB, evA, 0);
    agg1_kernel<<<(NN * 32 + 255) / 256, 256, 0, sB>>>(b1, 0);
    cudaEventRecord(evH0, sB);

    // ---- agg1 hh=1 on stream 0 (after gemm1 hh=1, needs CSR) ----
    cudaStreamWaitEvent(0, evCSR, 0);
    agg1_kernel<<<(NN * 32 + 255) / 256, 256>>>(b1, 1);

    // ---- join, gemm2 in two halves across streams, then agg2 ----
    cudaStreamWaitEvent(0, evH0, 0);
    cudaEventRecord(evX2, 0);
    cudaStreamWaitEvent(sB, evX2, 0);
    gemm2_mma_kernel<<<196, 256>>>(attS2, attD2, 0, 25088);
    gemm2_mma_kernel<<<195, 256, 0, sB>>>(attS2, attD2, 25088, NN);
    cudaEventRecord(evH0, sB);
    cudaStreamWaitEvent(0, evH0, 0);
    agg2_kernel<<<(NN * 32 + 255) / 256, 256>>>(b2, fcW, fcb, out);
}

// round 16
// speedup vs baseline: 1.0293x; 1.0293x over previous
#include <cuda_runtime.h>
#include <cuda_bf16.h>
#include <cuda_fp16.h>
#include <cstdint>

// Problem constants (fixed by the dataset)
#define NN      50000
#define EE      800000
#define IN_DIM  256
#define HEADS   8
#define C1      64
#define HC1     512          // HEADS*C1
#define C2      32
#define OUT_DIM 40
#define NEG_SLOPE 0.2f

#define SCAN_BLOCKS 49       // 49 * 1024 >= NN
#define NHALF 25088          // 196 * 128, split point for layer pipelining

// ---------------- scratch (device globals; no cudaMalloc allowed) ------------
__device__ __half g_xl1h[(size_t)NN * HC1];   // x @ W1  (fp16)
__device__ __half g_h1h [(size_t)NN * HC1];   // layer-1 output, relu (fp16)
__device__ __half g_xh  [(size_t)NN * IN_DIM];   // x in fp16
__device__ __half g_w1h [(size_t)IN_DIM * HC1];  // W1 fp16
__device__ __half g_w2hi[HC1 * C2];
__device__ __half g_w2lo[HC1 * C2];
__device__ __half g_xl2h[(size_t)NN * C2];    // layer-2 pre-act (fp16)
__device__ float g_as1[NN * HEADS];
__device__ float g_ad1[NN * HEADS];
__device__ float g_as2[NN], g_ad2[NN];
__device__ int   g_deg[NN];
__device__ int   g_incl[SCAN_BLOCKS * 1024];
__device__ int   g_bsum[SCAN_BLOCKS];
__device__ int   g_boff[SCAN_BLOCKS];
__device__ int   g_rowptr[NN + 1];
__device__ int   g_cursor[NN];
__device__ int   g_csrc[EE];

__device__ __forceinline__ float lrelu(float x) { return x > 0.f ? x : NEG_SLOPE * x; }

// ========================= PTX helpers =========================
__device__ __forceinline__ uint32_t smem_u32(const void* p) {
    uint32_t a;
    asm("{ .reg .u64 t; cvta.to.shared.u64 t, %1; cvt.u32.u64 %0, t; }" : "=r"(a) : "l"(p));
    return a;
}
__device__ __forceinline__ void ldsm_x4(uint32_t addr, uint32_t& r0, uint32_t& r1,
                                        uint32_t& r2, uint32_t& r3) {
    asm volatile("ldmatrix.sync.aligned.m8n8.x4.shared.b16 {%0,%1,%2,%3}, [%4];"
                 : "=r"(r0), "=r"(r1), "=r"(r2), "=r"(r3) : "r"(addr));
}
__device__ __forceinline__ void ldsm_x4_trans(uint32_t addr, uint32_t& r0, uint32_t& r1,
                                              uint32_t& r2, uint32_t& r3) {
    asm volatile("ldmatrix.sync.aligned.m8n8.x4.trans.shared.b16 {%0,%1,%2,%3}, [%4];"
                 : "=r"(r0), "=r"(r1), "=r"(r2), "=r"(r3) : "r"(addr));
}
__device__ __forceinline__ void mma_f16(float* d, const uint32_t* a, const uint32_t* b) {
    asm volatile(
        "mma.sync.aligned.m16n8k16.row.col.f32.f16.f16.f32 "
        "{%0,%1,%2,%3},{%4,%5,%6,%7},{%8,%9},{%0,%1,%2,%3};"
        : "+f"(d[0]), "+f"(d[1]), "+f"(d[2]), "+f"(d[3])
        : "r"(a[0]), "r"(a[1]), "r"(a[2]), "r"(a[3]), "r"(b[0]), "r"(b[1]));
}
__device__ __forceinline__ void cp16(uint32_t dst, const void* src, uint32_t sz) {
    asm volatile("cp.async.cg.shared.global [%0], [%1], 16, %2;"
                 :: "r"(dst), "l"(src), "r"(sz) : "memory");
}
// unpack 8 fp16 (one uint4) to 8 floats
__device__ __forceinline__ void unpack8(uint4 v, float* f) {
    float2 t;
    t = __half22float2(*(__half2*)&v.x); f[0] = t.x; f[1] = t.y;
    t = __half22float2(*(__half2*)&v.y); f[2] = t.x; f[3] = t.y;
    t = __half22float2(*(__half2*)&v.z); f[4] = t.x; f[5] = t.y;
    t = __half22float2(*(__half2*)&v.w); f[6] = t.x; f[7] = t.y;
}

// ===================== merged input prep kernel ================================
#define NXC (NN * IN_DIM / 4)
#define NWC (IN_DIM * HC1 / 4)
#define NW2C (HC1 * C2 / 4)
__global__ void split_all_kernel(const float* __restrict__ x, const float* __restrict__ w1,
                                 const float* __restrict__ w2) {
    int i = blockIdx.x * blockDim.x + threadIdx.x;
    if (i < NXC) {
        float4 v = ((const float4*)x)[i];
        __half2 a = __floats2half2_rn(v.x, v.y);
        __half2 b = __floats2half2_rn(v.z, v.w);
        ((uint2*)g_xh)[i] = make_uint2(*(uint32_t*)&a, *(uint32_t*)&b);
    } else if (i < NXC + NWC) {
        int k = i - NXC;
        float4 v = ((const float4*)w1)[k];
        __half2 a = __floats2half2_rn(v.x, v.y);
        __half2 b = __floats2half2_rn(v.z, v.w);
        ((uint2*)g_w1h)[k] = make_uint2(*(uint32_t*)&a, *(uint32_t*)&b);
    } else if (i < NXC + NWC + NW2C) {
        int k = i - NXC - NWC;
        float4 v = ((const float4*)w2)[k];
        __half h0 = __float2half_rn(v.x), h1 = __float2half_rn(v.y);
        __half h2 = __float2half_rn(v.z), h3 = __float2half_rn(v.w);
        __half l0 = __float2half_rn(v.x - __half2float(h0));
        __half l1 = __float2half_rn(v.y - __half2float(h1));
        __half l2 = __float2half_rn(v.z - __half2float(h2));
        __half l3 = __float2half_rn(v.w - __half2float(h3));
        __half2 p0 = __halves2half2(h0, h1), p1 = __halves2half2(h2, h3);
        __half2 q0 = __halves2half2(l0, l1), q1 = __halves2half2(l2, l3);
        ((uint2*)g_w2hi)[k] = make_uint2(*(uint32_t*)&p0, *(uint32_t*)&p1);
        ((uint2*)g_w2lo)[k] = make_uint2(*(uint32_t*)&q0, *(uint32_t*)&q1);
    }
}

// ======== GEMM1: xl1 = x @ W1, pure fp16, cp.async 3-stage pipeline ==========
#define ASTR 40     // fp16 per A smem row (32 + 8 pad)
#define BSTR 136    // fp16 per B smem row (128 + 8 pad)
#define OFF_A   0
#define OFF_B   10240
#define STAGE   18944
#define GEMM1_SMEM (3 * STAGE)

__global__ void __launch_bounds__(256, 2) gemm1_mma_kernel(const float* __restrict__ attS1,
                                                           const float* __restrict__ attD1) {
    extern __shared__ __align__(16) char smem[];
    const uint32_t sbase = smem_u32(smem);
    const int tid = threadIdx.x, wid = tid >> 5, lane = tid & 31;
    const int warpM = (wid & 3) * 32;
    const int warpN = (wid >> 2) * 64;
    const int mBase = blockIdx.x * 128;
    const int nBase = blockIdx.y * 128;

    float acc[2][8][4];
#pragma unroll
    for (int mi = 0; mi < 2; mi++)
#pragma unroll
        for (int ni = 0; ni < 8; ni++)
#pragma unroll
            for (int q = 0; q < 4; q++) acc[mi][ni][q] = 0.f;

    auto load_stage = [&](int ch, int buf) {
        const int k0 = ch * 32;
        const uint32_t sb = sbase + buf * STAGE;
#pragma unroll
        for (int it = 0; it < 2; it++) {
            int chunk = it * 256 + tid;          // 512 chunks (A)
            int r = chunk >> 2, c = (chunk & 3) * 8;
            int gr = mBase + r;
            uint32_t sz = (gr < NN) ? 16u : 0u;
            int grc = gr < NN ? gr : NN - 1;
            uint32_t so = (uint32_t)(r * ASTR + c) * 2;
            cp16(sb + OFF_A + so, &g_xh[(size_t)grc * IN_DIM + k0 + c], sz);
        }
#pragma unroll
        for (int it = 0; it < 2; it++) {
            int chunk = it * 256 + tid;          // 512 chunks (B)
            int r = chunk >> 4, c = (chunk & 15) * 8;
            uint32_t so = (uint32_t)(r * BSTR + c) * 2;
            cp16(sb + OFF_B + so, &g_w1h[(size_t)(k0 + r) * HC1 + nBase + c], 16);
        }
        asm volatile("cp.async.commit_group;" ::: "memory");
    };

    load_stage(0, 0);
    load_stage(1, 1);
    for (int ch = 0; ch < 8; ch++) {
        if (ch < 7) {
            asm volatile("cp.async.wait_group 1;" ::: "memory");
        } else {
            asm volatile("cp.async.wait_group 0;" ::: "memory");
        }
        __syncthreads();
        if (ch + 2 < 8) load_stage(ch + 2, (ch + 2) % 3);
        const uint32_t sb = sbase + (ch % 3) * STAGE;
#pragma unroll
        for (int ks = 0; ks < 2; ks++) {
            uint32_t av[2][4];
#pragma unroll
            for (int mi = 0; mi < 2; mi++) {
                int row = warpM + mi * 16 + (lane & 15);
                int col = ks * 16 + (lane >> 4) * 8;
                uint32_t off = (uint32_t)(row * ASTR + col) * 2;
                ldsm_x4(sb + OFF_A + off, av[mi][0], av[mi][1], av[mi][2], av[mi][3]);
            }
            uint32_t bv[8][2];
#pragma unroll
            for (int np = 0; np < 4; np++) {
                int krow = ks * 16 + (lane & 15);
                int col = warpN + np * 16 + (lane >> 4) * 8;
                uint32_t off = (uint32_t)(krow * BSTR + col) * 2;
                ldsm_x4_trans(sb + OFF_B + off, bv[np * 2][0], bv[np * 2][1],
                              bv[np * 2 + 1][0], bv[np * 2 + 1][1]);
            }
#pragma unroll
            for (int mi = 0; mi < 2; mi++)
#pragma unroll
                for (int ni = 0; ni < 8; ni++)
                    mma_f16(acc[mi][ni], av[mi], bv[ni]);
        }
    }

    // ---- epilogue 1: store xl1 (fp16) ----
#pragma unroll
    for (int mi = 0; mi < 2; mi++) {
#pragma unroll
        for (int ni = 0; ni < 8; ni++) {
            int row0 = mBase + warpM + mi * 16 + (lane >> 2);
            int col = nBase + warpN + ni * 8 + (lane & 3) * 2;
            if (row0 < NN)
                *(__half2*)(&g_xl1h[(size_t)row0 * HC1 + col]) =
                    __floats2half2_rn(acc[mi][ni][0], acc[mi][ni][1]);
            int row1 = row0 + 8;
            if (row1 < NN)
                *(__half2*)(&g_xl1h[(size_t)row1 * HC1 + col]) =
                    __floats2half2_rn(acc[mi][ni][2], acc[mi][ni][3]);
        }
    }

    // ---- epilogue 2: fused a_src / a_dst (warp owns one complete head) ----
    {
        const int h = blockIdx.y * 2 + (wid >> 2);
        float sS[8][2], sD[8][2];
        int cb = h * C1 + (lane & 3) * 2;
#pragma unroll
        for (int ni = 0; ni < 8; ni++) {
            sS[ni][0] = __ldg(&attS1[cb + ni * 8]);
            sS[ni][1] = __ldg(&attS1[cb + ni * 8 + 1]);
            sD[ni][0] = __ldg(&attD1[cb + ni * 8]);
            sD[ni][1] = __ldg(&attD1[cb + ni * 8 + 1]);
        }
#pragma unroll
        for (int mi = 0; mi < 2; mi++) {
            float rs0 = 0.f, rs1 = 0.f, rd0 = 0.f, rd1 = 0.f;
#pragma unroll
            for (int ni = 0; ni < 8; ni++) {
                rs0 = fmaf(acc[mi][ni][0], sS[ni][0], fmaf(acc[mi][ni][1], sS[ni][1], rs0));
                rd0 = fmaf(acc[mi][ni][0], sD[ni][0], fmaf(acc[mi][ni][1], sD[ni][1], rd0));
                rs1 = fmaf(acc[mi][ni][2], sS[ni][0], fmaf(acc[mi][ni][3], sS[ni][1], rs1));
                rd1 = fmaf(acc[mi][ni][2], sD[ni][0], fmaf(acc[mi][ni][3], sD[ni][1], rd1));
            }
#pragma unroll
            for (int off = 1; off <= 2; off <<= 1) {
                rs0 += __shfl_xor_sync(0xffffffffu, rs0, off);
                rd0 += __shfl_xor_sync(0xffffffffu, rd0, off);
                rs1 += __shfl_xor_sync(0xffffffffu, rs1, off);
                rd1 += __shfl_xor_sync(0xffffffffu, rd1, off);
            }
            if ((lane & 3) == 0) {
                int row0 = mBase + warpM + mi * 16 + (lane >> 2);
                if (row0 < NN) { g_as1[row0 * 8 + h] = rs0; g_ad1[row0 * 8 + h] = rd0; }
                int row1 = row0 + 8;
                if (row1 < NN) { g_as1[row1 * 8 + h] = rs1; g_ad1[row1 * 8 + h] = rd1; }
            }
        }
    }
}

// ---------------------------- CSR construction -------------------------------
__global__ void hist_kernel(const int* __restrict__ dst) {
    int e = blockIdx.x * blockDim.x + threadIdx.x;
    if (e < EE) atomicAdd(&g_deg[dst[e]], 1);
}
__global__ void scanA_kernel() {
    __shared__ int sh[1024];
    int i = blockIdx.x * 1024 + threadIdx.x;
    int v = (i < NN) ? g_deg[i] : 0;
    sh[threadIdx.x] = v;
    __syncthreads();
#pragma unroll
    for (int off = 1; off < 1024; off <<= 1) {
        int t = (threadIdx.x >= off) ? sh[threadIdx.x - off] : 0;
        __syncthreads();
        sh[threadIdx.x] += t;
        __syncthreads();
    }
    g_incl[i] = sh[threadIdx.x];
    if (threadIdx.x == 1023) g_bsum[blockIdx.x] = sh[1023];
}
__global__ void scanB_kernel() {   // 1 block, 64 threads
    __shared__ int sh[64];
    int t = threadIdx.x;
    int v = (t < SCAN_BLOCKS) ? g_bsum[t] : 0;
    sh[t] = v;
    __syncthreads();
#pragma unroll
    for (int off = 1; off < 64; off <<= 1) {
        int u = (t >= off) ? sh[t - off] : 0;
        __syncthreads();
        sh[t] += u;
        __syncthreads();
    }
    if (t < SCAN_BLOCKS) g_boff[t] = sh[t] - v;   // exclusive
}
__global__ void scanC_kernel() {
    int i = blockIdx.x * 1024 + threadIdx.x;
    if (i < NN) {
        int ex = g_boff[blockIdx.x] + g_incl[i] - g_deg[i];
        g_rowptr[i] = ex;
        g_cursor[i] = ex;
    }
    if (i == 0) g_rowptr[NN] = EE;
}
__global__ void scatter_kernel(const int* __restrict__ src, const int* __restrict__ dst) {
    int e = blockIdx.x * blockDim.x + threadIdx.x;
    if (e >= EE) return;
    int d = dst[e];
    int pos = atomicAdd(&g_cursor[d], 1);
    g_csrc[pos] = src[e];
}

// ---- layer-1 fused softmax+aggregation: warp per node, prefetched batches ----
__global__ void agg1_kernel(const float* __restrict__ b1, int nodeBeg, int nodeEnd) {
    int w = nodeBeg + ((blockIdx.x * blockDim.x + threadIdx.x) >> 5);
    int lane = threadIdx.x & 31;
    if (w >= nodeEnd) return;
    const int h = lane >> 2;
    const int e4 = lane & 3;
    const int idx8 = w * 8 + h;
    const float ad = g_ad1[idx8];
    const float pself = __expf(lrelu(g_as1[idx8] + ad));

    float acc[16];
    {
        const uint4* xr = (const uint4*)(g_xl1h + (size_t)w * HC1 + lane * 16);
        uint4 v0 = xr[0], v1 = xr[1];
        unpack8(v0, acc); unpack8(v1, acc + 8);
#pragma unroll
        for (int i = 0; i < 16; i++) acc[i] *= pself;
    }
    float dacc = 0.f;

    const int beg = g_rowptr[w], end = g_rowptr[w + 1];
    const int qb = lane & 28;

    int s_cur = 0; float a_cur = 0.f;
    {
        int j = beg + e4;
        if (j < end) { s_cur = g_csrc[j]; a_cur = __ldg(&g_as1[s_cur * 8 + h]); }
    }
    for (int j0 = beg; j0 < end; j0 += 4) {
        int s_nxt = 0; float a_nxt = 0.f;
        int jn = j0 + 4 + e4;
        if (jn < end) { s_nxt = g_csrc[jn]; a_nxt = __ldg(&g_as1[s_nxt * 8 + h]); }

        bool valid = (j0 + e4) < end;
        float p_l = valid ? __expf(lrelu(a_cur + ad)) : 0.f;
        dacc += p_l;
        int cnt = end - j0;
#pragma unroll
        for (int t = 0; t < 4; t++) {
            if (t < cnt) {
                float p = __shfl_sync(0xffffffffu, p_l, qb | t);
                int   s = __shfl_sync(0xffffffffu, s_cur, qb | t);
                const uint4* sr = (const uint4*)(g_xl1h + (size_t)s * HC1 + lane * 16);
                uint4 u0 = sr[0], u1 = sr[1];
                float bq[16];
                unpack8(u0, bq); unpack8(u1, bq + 8);
#pragma unroll
                for (int i = 0; i < 16; i++) acc[i] = fmaf(p, bq[i], acc[i]);
            }
        }
        s_cur = s_nxt; a_cur = a_nxt;
    }
    dacc += __shfl_xor_sync(0xffffffffu, dacc, 1);
    dacc += __shfl_xor_sync(0xffffffffu, dacc, 2);
    float inv = 1.f / (dacc + pself + 1e-16f);

    float bv[16];
    {
        const float4* bb = (const float4*)(b1 + lane * 16);
        float4 t0 = bb[0], t1 = bb[1], t2 = bb[2], t3 = bb[3];
        bv[0] = t0.x; bv[1] = t0.y; bv[2]  = t0.z; bv[3]  = t0.w;
        bv[4] = t1.x; bv[5] = t1.y; bv[6]  = t1.z; bv[7]  = t1.w;
        bv[8] = t2.x; bv[9] = t2.y; bv[10] = t2.z; bv[11] = t2.w;
        bv[12] = t3.x; bv[13] = t3.y; bv[14] = t3.z; bv[15] = t3.w;
    }
    uint32_t r[8];
#pragma unroll
    for (int i = 0; i < 8; i++) {
        float f0 = fmaxf(fmaf(acc[2 * i],     inv, bv[2 * i]),     0.f);
        float f1 = fmaxf(fmaf(acc[2 * i + 1], inv, bv[2 * i + 1]), 0.f);
        __half2 hh = __floats2half2_rn(f0, f1);
        r[i] = *(uint32_t*)&hh;
    }
    uint4* hw = (uint4*)(g_h1h + (size_t)w * HC1 + lane * 16);
    hw[0] = make_uint4(r[0], r[1], r[2], r[3]);
    hw[1] = make_uint4(r[4], r[5], r[6], r[7]);
}

// ==== GEMM2: xl2 = h1 @ W2 (rows [nodeBeg,nodeEnd)), fp16 A + fp16 hi/lo B ===
#define A2STR 40
#define B2STR 40
__global__ void __launch_bounds__(256) gemm2_mma_kernel(const float* __restrict__ attS2,
                                                        const float* __restrict__ attD2,
                                                        int nodeBeg, int nodeEnd) {
    __shared__ __align__(16) __half sA[128 * A2STR];
    __shared__ __align__(16) __half sBhi[32 * B2STR], sBlo[32 * B2STR];
    const int tid = threadIdx.x, wid = tid >> 5, lane = tid & 31;
    const int mBase = nodeBeg + blockIdx.x * 128;
    const int warpM = wid * 16;

    const int ar = tid >> 1, ak = (tid & 1) * 16;
    int grow = mBase + ar; if (grow >= nodeEnd) grow = nodeEnd - 1;
    const __half* abase = g_h1h + (size_t)grow * HC1 + ak;
    const bool bhi_role = tid < 128;
    const int bk = (tid & 127) >> 2, bseg = (tid & 3) * 8;
    const __half* bsrc = (bhi_role ? g_w2hi : g_w2lo) + bk * C2 + bseg;

    float acc[4][4];
#pragma unroll
    for (int ni = 0; ni < 4; ni++)
#pragma unroll
        for (int q = 0; q < 4; q++) acc[ni][q] = 0.f;

    uint4 ra0 = *(const uint4*)(abase);
    uint4 ra1 = *(const uint4*)(abase + 8);
    uint4 rb = *(const uint4*)bsrc;

    const uint32_t sAB = smem_u32(sA);
    const uint32_t sBhiB = smem_u32(sBhi), sBloB = smem_u32(sBlo);

    for (int ch = 0; ch < 16; ch++) {
        *(uint4*)(&sA[ar * A2STR + ak])     = ra0;
        *(uint4*)(&sA[ar * A2STR + ak + 8]) = ra1;
        __half* bdst = (bhi_role ? sBhi : sBlo) + bk * B2STR + bseg;
        *(uint4*)bdst = rb;
        __syncthreads();
        if (ch < 15) {
            const __half* an = abase + (ch + 1) * 32;
            ra0 = *(const uint4*)(an);
            ra1 = *(const uint4*)(an + 8);
            rb = *(const uint4*)(bsrc + (size_t)(ch + 1) * 32 * C2);
        }
#pragma unroll
        for (int ks = 0; ks < 2; ks++) {
            uint32_t av[4];
            int row = warpM + (lane & 15);
            int col = ks * 16 + (lane >> 4) * 8;
            uint32_t offA = (uint32_t)(row * A2STR + col) * 2;
            ldsm_x4(sAB + offA, av[0], av[1], av[2], av[3]);
            uint32_t bh[4][2], bl[4][2];
            int krow = ks * 16 + (lane & 15);
#pragma unroll
            for (int np = 0; np < 2; np++) {
                int bcol = np * 16 + (lane >> 4) * 8;
                uint32_t offB = (uint32_t)(krow * B2STR + bcol) * 2;
                ldsm_x4_trans(sBhiB + offB, bh[np * 2][0], bh[np * 2][1],
                              bh[np * 2 + 1][0], bh[np * 2 + 1][1]);
                ldsm_x4_trans(sBloB + offB, bl[np * 2][0], bl[np * 2][1],
                              bl[np * 2 + 1][0], bl[np * 2 + 1][1]);
            }
#pragma unroll
            for (int ni = 0; ni < 4; ni++) {
                mma_f16(acc[ni], av, bh[ni]);
                mma_f16(acc[ni], av, bl[ni]);
            }
        }
        __syncthreads();
    }

    int row0 = mBase + warpM + (lane >> 2);
    int row1 = row0 + 8;
    float rs0 = 0.f, rd0 = 0.f, rs1 = 0.f, rd1 = 0.f;
#pragma unroll
    for (int ni = 0; ni < 4; ni++) {
        int col = ni * 8 + (lane & 3) * 2;
        if (row0 < nodeEnd)
            *(__half2*)(&g_xl2h[(size_t)row0 * C2 + col]) =
                __floats2half2_rn(acc[ni][0], acc[ni][1]);
        if (row1 < nodeEnd)
            *(__half2*)(&g_xl2h[(size_t)row1 * C2 + col]) =
                __floats2half2_rn(acc[ni][2], acc[ni][3]);
        float s0 = __ldg(&attS2[col]), s1 = __ldg(&attS2[col + 1]);
        float d0 = __ldg(&attD2[col]), d1 = __ldg(&attD2[col + 1]);
        rs0 = fmaf(acc[ni][0], s0, fmaf(acc[ni][1], s1, rs0));
        rd0 = fmaf(acc[ni][0], d0, fmaf(acc[ni][1], d1, rd0));
        rs1 = fmaf(acc[ni][2], s0, fmaf(acc[ni][3], s1, rs1));
        rd1 = fmaf(acc[ni][2], d0, fmaf(acc[ni][3], d1, rd1));
    }
#pragma unroll
    for (int off = 1; off <= 2; off <<= 1) {
        rs0 += __shfl_xor_sync(0xffffffffu, rs0, off);
        rd0 += __shfl_xor_sync(0xffffffffu, rd0, off);
        rs1 += __shfl_xor_sync(0xffffffffu, rs1, off);
        rd1 += __shfl_xor_sync(0xffffffffu, rd1, off);
    }
    if ((lane & 3) == 0) {
        if (row0 < nodeEnd) { g_as2[row0] = rs0; g_ad2[row0] = rd0; }
        if (row1 < nodeEnd) { g_as2[row1] = rs1; g_ad2[row1] = rd1; }
    }
}

// ---- layer-2 fused softmax+aggregation + fc head: warp per node --------------
__global__ void __launch_bounds__(256) agg2_kernel(const float* __restrict__ b2,
                                                   const float* __restrict__ fcW,
                                                   const float* __restrict__ fcb,
                                                   float* __restrict__ out) {
    __shared__ float fs[C2 * OUT_DIM];
    __shared__ float fb[OUT_DIM];
    for (int i = threadIdx.x; i < C2 * OUT_DIM; i += 256) fs[i] = fcW[i];
    if (threadIdx.x < OUT_DIM) fb[threadIdx.x] = fcb[threadIdx.x];
    __syncthreads();

    int w = (blockIdx.x * blockDim.x + threadIdx.x) >> 5;
    int lane = threadIdx.x & 31;
    if (w >= NN) return;
    float ad = g_ad2[w];
    float pself = __expf(lrelu(g_as2[w] + ad));
    float acc0 = pself * __half2float(g_xl2h[(size_t)w * C2 + lane]);
    float acc1 = 0.f;
    float dacc = 0.f;
    const int beg = g_rowptr[w], end = g_rowptr[w + 1];

    int s_cur = 0; float a_cur = 0.f;
    {
        int j = beg + lane;
        if (j < end) { s_cur = g_csrc[j]; a_cur = __ldg(&g_as2[s_cur]); }
    }
    int j0 = beg;
    for (; j0 + 32 <= end; j0 += 32) {
        int s_nxt = 0; float a_nxt = 0.f;
        int jn = j0 + 32 + lane;
        if (jn < end) { s_nxt = g_csrc[jn]; a_nxt = __ldg(&g_as2[s_nxt]); }
        float p_l = __expf(lrelu(a_cur + ad));
        dacc += p_l;
#pragma unroll
        for (int t = 0; t < 32; t += 2) {
            float p0 = __shfl_sync(0xffffffffu, p_l, t);
            int   q0 = __shfl_sync(0xffffffffu, s_cur, t);
            float p1 = __shfl_sync(0xffffffffu, p_l, t + 1);
            int   q1 = __shfl_sync(0xffffffffu, s_cur, t + 1);
            acc0 = fmaf(p0, __half2float(g_xl2h[(size_t)q0 * C2 + lane]), acc0);
            acc1 = fmaf(p1, __half2float(g_xl2h[(size_t)q1 * C2 + lane]), acc1);
        }
        s_cur = s_nxt; a_cur = a_nxt;
    }
    if (j0 < end) {
        bool valid = (j0 + lane) < end;
        float p_l = valid ? __expf(lrelu(a_cur + ad)) : 0.f;
        dacc += p_l;
        int cnt = end - j0;
        for (int t = 0; t < cnt; t++) {
            float p = __shfl_sync(0xffffffffu, p_l, t);
            int   s = __shfl_sync(0xffffffffu, s_cur, t);
            acc0 = fmaf(p, __half2float(g_xl2h[(size_t)s * C2 + lane]), acc0);
        }
    }
    float acc = acc0 + acc1;
#pragma unroll
    for (int off = 16; off; off >>= 1) dacc += __shfl_xor_sync(0xffffffffu, dacc, off);
    float inv = 1.f / (dacc + pself + 1e-16f);
    float emb = fmaxf(fmaf(acc, inv, b2[lane]), 0.f);
    out[(size_t)w * C2 + lane] = emb;

    float l1 = fb[lane];
    float l2 = (lane < OUT_DIM - 32) ? fb[32 + lane] : 0.f;
#pragma unroll
    for (int c = 0; c < C2; c++) {
        float e = __shfl_sync(0xffffffffu, emb, c);
        l1 = fmaf(e, fs[c * OUT_DIM + lane], l1);
        if (lane < OUT_DIM - 32) l2 = fmaf(e, fs[c * OUT_DIM + 32 + lane], l2);
    }
    float* lg = out + (size_t)NN * C2 + (size_t)w * OUT_DIM;
    lg[lane] = l1;
    if (lane < OUT_DIM - 32) lg[32 + lane] = l2;
}

// ------------------------------------------------------------------------------
extern "C" void kernel_launch(void* const* d_in, const int* in_sizes, int n_in,
                              void* d_out, int out_size) {
    const float* x     = (const float*)d_in[0];
    const int*   ei    = (const int*)  d_in[1];
    const float* W1    = (const float*)d_in[2];
    const float* attS1 = (const float*)d_in[3];
    const float* attD1 = (const float*)d_in[4];
    const float* b1    = (const float*)d_in[5];
    const float* W2    = (const float*)d_in[6];
    const float* attS2 = (const float*)d_in[7];
    const float* attD2 = (const float*)d_in[8];
    const float* b2    = (const float*)d_in[9];
    const float* fcW   = (const float*)d_in[10];
    const float* fcb   = (const float*)d_in[11];
    float* out = (float*)d_out;

    const int* src = ei;
    const int* dst = ei + EE;

    // fixed auxiliary stream + events (created once; same captured DAG each call)
    static cudaStream_t sB = [] { cudaStream_t s; cudaStreamCreateWithFlags(&s, cudaStreamNonBlocking); return s; }();
    static cudaEvent_t evFork = [] { cudaEvent_t e; cudaEventCreateWithFlags(&e, cudaEventDisableTiming); return e; }();
    static cudaEvent_t evCSR  = [] { cudaEvent_t e; cudaEventCreateWithFlags(&e, cudaEventDisableTiming); return e; }();
    static cudaEvent_t evG1   = [] { cudaEvent_t e; cudaEventCreateWithFlags(&e, cudaEventDisableTiming); return e; }();
    static cudaEvent_t evHi   = [] { cudaEvent_t e; cudaEventCreateWithFlags(&e, cudaEventDisableTiming); return e; }();

    cudaFuncSetAttribute(gemm1_mma_kernel, cudaFuncAttributeMaxDynamicSharedMemorySize,
                         GEMM1_SMEM);

    // ---- fork: CSR chain on stream B, shadowed by split+gemm1 ----
    cudaEventRecord(evFork, 0);
    cudaStreamWaitEvent(sB, evFork, 0);

    void* degp = nullptr;
    cudaGetSymbolAddress(&degp, g_deg);
    cudaMemsetAsync(degp, 0, NN * sizeof(int), sB);
    hist_kernel<<<(EE + 255) / 256, 256, 0, sB>>>(dst);
    scanA_kernel<<<SCAN_BLOCKS, 1024, 0, sB>>>();
    scanB_kernel<<<1, 64, 0, sB>>>();
    scanC_kernel<<<SCAN_BLOCKS, 1024, 0, sB>>>();
    scatter_kernel<<<(EE + 255) / 256, 256, 0, sB>>>(src, dst);
    cudaEventRecord(evCSR, sB);

    // ---- main stream: merged split (x, W1, W2) + gemm1 ----
    split_all_kernel<<<(NXC + NWC + NW2C + 255) / 256, 256>>>(x, W1, W2);
    {
        dim3 grid((NN + 127) / 128, HC1 / 128);
        gemm1_mma_kernel<<<grid, 256, GEMM1_SMEM>>>(attS1, attD1);
    }
    cudaEventRecord(evG1, 0);

    // ---- layer 1 agg + layer 2 gemm, pipelined in node halves ----
    cudaStreamWaitEvent(0, evCSR, 0);
    agg1_kernel<<<(NHALF * 32 + 255) / 256, 256>>>(b1, 0, NHALF);
    gemm2_mma_kernel<<<NHALF / 128, 256>>>(attS2, attD2, 0, NHALF);

    cudaStreamWaitEvent(sB, evG1, 0);
    agg1_kernel<<<((NN - NHALF) * 32 + 255) / 256, 256, 0, sB>>>(b1, NHALF, NN);
    gemm2_mma_kernel<<<(NN - NHALF + 127) / 128, 256, 0, sB>>>(attS2, attD2, NHALF, NN);
    cudaEventRecord(evHi, sB);

    // ---- join, then layer-2 agg + fused fc head ----
    cudaStreamWaitEvent(0, evHi, 0);
    agg2_kernel<<<(NN * 32 + 255) / 256, 256>>>(b2, fcW, fcb, out);
}